// round 14
// baseline (speedup 1.0000x reference)
#include <cuda_runtime.h>
#include <math.h>

#define Bb 16
#define Nn 64
#define Cc 80
#define Hh 128
#define Ww 128
#define HW (Hh*Ww)
#define NB (Bb*Nn)
#define RMAX 16
#define EPS32 1.1920929e-07f
#define TOTAL (Bb*Cc*HW)

#define BG_BLOCKS 2560
#define N4 (TOTAL/4)              // 5,242,880 float4
#define BLK4 (N4/BG_BLOCKS)       // 2048 float4 per bg block = 8 * 256

// Persistent scalars only (no dense scratch at all anymore).
// Invariant between launches: all zero; the finalize block rezeros them.
__device__ double g_acc_bg;      // sum of lg2(1-p)*p^2 (scale by -ln2 at end)
__device__ double g_acc_c;       // focal corrections at ct>0 pixels
__device__ double g_acc_wh, g_acc_of;
__device__ int   g_af;
__device__ int   g_done;

// ---------------------------------------------------------------------------
__device__ __forceinline__ float block_reduce(float v) {
    __shared__ float sh[32];
    int lane = threadIdx.x & 31;
    int wid  = threadIdx.x >> 5;
    #pragma unroll
    for (int o = 16; o > 0; o >>= 1) v += __shfl_down_sync(0xffffffffu, v, o);
    if (lane == 0) sh[wid] = v;
    __syncthreads();
    int nw = (blockDim.x + 31) >> 5;
    v = (threadIdx.x < nw) ? sh[threadIdx.x] : 0.0f;
    if (wid == 0) {
        #pragma unroll
        for (int o = 16; o > 0; o >>= 1) v += __shfl_down_sync(0xffffffffu, v, o);
    }
    return v;  // valid on thread 0
}

__device__ __forceinline__ float f_bg_precise(float p) {
    return -__logf(1.0f - p + 1e-12f) * (p * p);
}

// packed f32x2 helpers
#define PACK2(out, lo, hi) asm("mov.b64 %0, {%1, %2};" : "=l"(out) : "f"(lo), "f"(hi))
#define UNPACK2(lo, hi, in) asm("mov.b64 {%0, %1}, %2;" : "=f"(lo), "=f"(hi) : "l"(in))
#define FMA2(out, a, b, c) asm("fma.rn.f32x2 %0, %1, %2, %3;" : "=l"(out) : "l"(a), "l"(b), "l"(c))
#define MUL2(out, a, b)    asm("mul.rn.f32x2 %0, %1, %2;" : "=l"(out) : "l"(a), "l"(b))
#define LG2(out, in)       asm("lg2.approx.f32 %0, %1;" : "=f"(out) : "f"(in))

// acc += lg2(1-p) * p^2   (elementwise on a packed pair)
__device__ __forceinline__ void bg_pair(unsigned long long P,
                                        unsigned long long NEG2,
                                        unsigned long long ONE2,
                                        unsigned long long& ACC) {
    unsigned long long T, Q, L;
    FMA2(T, P, NEG2, ONE2);         // t = 1 - p
    float t0, t1, l0, l1;
    UNPACK2(t0, t1, T);
    LG2(l0, t0);
    LG2(l1, t1);
    PACK2(L, l0, l1);
    MUL2(Q, P, P);                  // p^2
    FMA2(ACC, L, Q, ACC);           // acc += lg2(t) * p^2
}

__device__ __forceinline__ void bg_quad(float4 v,
                                        unsigned long long NEG2,
                                        unsigned long long ONE2,
                                        unsigned long long& A0,
                                        unsigned long long& A1) {
    unsigned long long P;
    PACK2(P, v.x, v.y); bg_pair(P, NEG2, ONE2, A0);
    PACK2(P, v.z, v.w); bg_pair(P, NEG2, ONE2, A1);
}

// ---------------------------------------------------------------------------
// ONE fused kernel, no inter-role dependencies:
//   blocks [0, BG_BLOCKS)   -> dense background lg2-sum over 84 MB
//   blocks [BG_BLOCKS,+NB)  -> per-box correction, fully self-contained:
//                              recomputes its batch's 64 box params in smem
//                              and evaluates the scatter-max ANALYTICALLY
//                              (max over same-(batch,class) boxes). No
//                              scratch arrays, no atomics on maps, no gate.
// The LAST completing block assembles the loss and rezeros accumulators.
__global__ void __launch_bounds__(256) k_fused(const float4* __restrict__ cp4,
                                               const float*  __restrict__ boxes,
                                               const int*    __restrict__ labels,
                                               const float*  __restrict__ wh,
                                               const float*  __restrict__ off,
                                               float* __restrict__ out) {
    int bid = blockIdx.x;

    if (bid < BG_BLOCKS) {
        // ========================== BG role ==============================
        const float4* p = cp4 + (size_t)bid * BLK4 + threadIdx.x;
        unsigned long long ONE2, NEG2, A0 = 0, A1 = 0, A2 = 0, A3 = 0;
        PACK2(ONE2, 1.0f, 1.0f);
        PACK2(NEG2, -1.0f, -1.0f);
        #pragma unroll
        for (int r = 0; r < 2; r++) {           // BLK4 = 8 * 256, exact
            float4 v0 = p[r*1024 +   0];
            float4 v1 = p[r*1024 + 256];
            float4 v2 = p[r*1024 + 512];
            float4 v3 = p[r*1024 + 768];
            bg_quad(v0, NEG2, ONE2, A0, A1);
            bg_quad(v1, NEG2, ONE2, A2, A3);
            bg_quad(v2, NEG2, ONE2, A0, A1);
            bg_quad(v3, NEG2, ONE2, A2, A3);
        }
        float a0, a1, b0, b1, c0, c1, d0, d1;
        UNPACK2(a0, a1, A0); UNPACK2(b0, b1, A1);
        UNPACK2(c0, c1, A2); UNPACK2(d0, d1, A3);
        float s = ((a0 + a1) + (b0 + b1)) + ((c0 + c1) + (d0 + d1));
        float bs = block_reduce(s);
        if (threadIdx.x == 0 && bs != 0.0f) atomicAdd(&g_acc_bg, (double)bs);
    } else {
        // ========================== Correction role ======================
        int t = bid - BG_BLOCKS;             // box id
        int b = t >> 6, n = t & 63;

        __shared__ float sc_cx[Nn], sc_cy[Nn], sc_sw[Nn], sc_sh[Nn], sc_inv[Nn];
        __shared__ int   sc_cxi[Nn], sc_cyi[Nn], sc_rw[Nn], sc_cls[Nn];
        __shared__ int   sc_glist[Nn];
        __shared__ int   sc_gcnt;

        if (threadIdx.x < Nn) {
            int i = b * Nn + threadIdx.x;
            float x1 = boxes[4*i+0], y1 = boxes[4*i+1];
            float x2 = boxes[4*i+2], y2 = boxes[4*i+3];
            const float wr = 0.25f, hr = 0.25f;        // W/512, H/512
            float cx = ((x1 + x2) * wr) * 0.5f;
            float cy = ((y1 + y2) * hr) * 0.5f;
            int cxi = (int)floorf(cx);
            int cyi = (int)floorf(cy);
            float sw = (x2 - x1) * wr;
            float sh = (y2 - y1) * hr;

            // gaussian radius, reference fp32 op order
            float h = sh, w = sw;
            float b1 = h + w;
            float c1 = ((w * h) * 0.7f) / 1.3f;
            float sq1 = sqrtf(b1*b1 - 4.0f*c1);
            float r1 = (b1 - sq1) * 0.5f;
            float b2 = 2.0f * (h + w);
            float c2 = (0.7f * w) * h;
            float sq2 = sqrtf(b2*b2 - 16.0f*c2);
            float r2 = (b2 - sq2) * 0.125f;
            float b3 = -0.6f * (h + w);
            float c3 = (-0.7f * w) * h;
            float sq3 = sqrtf(b3*b3 - 4.8f*c3);
            float r3 = (b3 + sq3) / 2.4f;
            float rm = fminf(fminf(r1, r2), r3);
            int rad = (int)fmaxf(0.0f, floorf(rm));

            float d = (float)(2*rad + 1);
            float sig2 = ((2.0f * d) / 6.0f) * (d / 6.0f);

            sc_cx[threadIdx.x]  = cx;   sc_cy[threadIdx.x]  = cy;
            sc_sw[threadIdx.x]  = sw;   sc_sh[threadIdx.x]  = sh;
            sc_inv[threadIdx.x] = 1.0f / sig2;
            sc_cxi[threadIdx.x] = cxi;  sc_cyi[threadIdx.x] = cyi;
            sc_rw[threadIdx.x]  = rad < RMAX ? rad : RMAX;
            sc_cls[threadIdx.x] = labels[i];
        }
        __syncthreads();
        int cls = sc_cls[n];
        if (threadIdx.x == 0) {
            int c = 0;
            for (int m = 0; m < Nn; m++)
                if (sc_cls[m] == cls) sc_glist[c++] = m;
            sc_gcnt = c;
        }
        __syncthreads();

        int gcnt = sc_gcnt;
        int rw = sc_rw[n], wdim = 2*rw + 1, nwin = wdim * wdim;
        int cxi = sc_cxi[n], cyi = sc_cyi[n];
        int plane = ((b * Cc + cls) * Hh) * Ww;
        const float* cp = (const float*)cp4;

        float delta = 0.0f;
        int hits1 = 0;
        for (int i = threadIdx.x; i < nwin; i += blockDim.x) {
            int dy = i / wdim - rw;
            int dx = i - (dy + rw) * wdim - rw;
            int y = cyi + dy, x = cxi + dx;
            if ((unsigned)y < (unsigned)Hh && (unsigned)x < (unsigned)Ww) {
                // ownership: first group member whose window contains (y,x)
                int owner = -1;
                for (int gi = 0; gi < gcnt; gi++) {
                    int m = sc_glist[gi];
                    int ady = y - sc_cyi[m]; ady = ady < 0 ? -ady : ady;
                    int adx = x - sc_cxi[m]; adx = adx < 0 ? -adx : adx;
                    if (ady <= sc_rw[m] && adx <= sc_rw[m]) { owner = m; break; }
                }
                if (owner == n) {
                    // analytic scatter-max over containing group members
                    float v = 0.0f;
                    for (int gi = 0; gi < gcnt; gi++) {
                        int m = sc_glist[gi];
                        int ddy = y - sc_cyi[m];
                        int ddx = x - sc_cxi[m];
                        int ady = ddy < 0 ? -ddy : ddy;
                        int adx = ddx < 0 ? -ddx : ddx;
                        if (ady <= sc_rw[m] && adx <= sc_rw[m]) {
                            float d2 = (float)(ddx*ddx + ddy*ddy);
                            v = fmaxf(v, expf(-d2 * sc_inv[m]));
                        }
                    }
                    float pv = cp[plane + y * Ww + x];
                    float fb = f_bg_precise(pv);
                    float om = 1.0f - v;
                    float om2 = om * om;
                    delta += fb * (om2 * om2 - 1.0f);
                    if (v == 1.0f) {
                        float q = 1.0f - pv;
                        delta += -__logf(pv + 1e-12f) * (q * q);
                        hits1++;
                    }
                }
            }
        }

        float bs = block_reduce(delta);
        __shared__ int sh_h[32];
        {   // block-reduce hits1
            int lane = threadIdx.x & 31, wid = threadIdx.x >> 5;
            #pragma unroll
            for (int o = 16; o > 0; o >>= 1) hits1 += __shfl_down_sync(0xffffffffu, hits1, o);
            if (lane == 0) sh_h[wid] = hits1;
            __syncthreads();
            hits1 = (threadIdx.x < 8) ? sh_h[threadIdx.x] : 0;
            if (wid == 0) {
                #pragma unroll
                for (int o = 4; o > 0; o >>= 1) hits1 += __shfl_down_sync(0xffffffffu, hits1, o);
            }
        }

        if (threadIdx.x == 0) {
            if (bs != 0.0f) atomicAdd(&g_acc_c, (double)bs);
            if (hits1)      atomicAdd(&g_af, hits1);
            // wh / offset: this box is the winner at its center pixel iff
            // no LATER box of the same batch has the same (cxi, cyi)
            // (last-wins semantics of the reference scatter .set)
            bool win = true;
            for (int m = n + 1; m < Nn; m++)
                if (sc_cxi[m] == cxi && sc_cyi[m] == cyi) { win = false; break; }
            if (win) {
                int pix = cyi * Ww + cxi;
                const float* wp = wh  + (size_t)b * 2 * HW;
                const float* op = off + (size_t)b * 2 * HW;
                float fx = sc_cx[n] - (float)cxi;
                float fy = sc_cy[n] - (float)cyi;
                float cw = fabsf(wp[pix] - sc_sw[n]) + fabsf(wp[HW + pix] - sc_sh[n]);
                float co = fabsf(op[pix] - fx) + fabsf(op[HW + pix] - fy);
                atomicAdd(&g_acc_wh, (double)cw);
                atomicAdd(&g_acc_of, (double)co);
            }
        }
    }

    // ---- completion: the LAST block of the grid finalizes ----
    __syncthreads();
    if (threadIdx.x == 0) {
        __threadfence();
        int done = atomicAdd(&g_done, 1);
        if (done == gridDim.x - 1) {
            double accc  = atomicAdd(&g_acc_c, 0.0);
            double accbg = atomicAdd(&g_acc_bg, 0.0);
            double accwh = atomicAdd(&g_acc_wh, 0.0);
            double accof = atomicAdd(&g_acc_of, 0.0);
            int afi      = atomicAdd(&g_af, 0);
            float af = fmaxf(1.0f, (float)afi);
            double bg = -0.693147180559945309 * accbg;   // -ln2 * lg2-sum
            float lc = (float)(bg + accc) / (af + EPS32);
            float lw = (0.1f * (float)accwh) / (af * 2.0f + EPS32);
            float lo = (float)accof / (af * 2.0f + EPS32);
            out[0] = lc + lw + lo;
            // restore zero invariant for next graph replay
            g_acc_bg = 0.0; g_acc_c = 0.0; g_acc_wh = 0.0; g_acc_of = 0.0;
            g_af = 0; g_done = 0;
            __threadfence();
        }
    }
}

// ---------------------------------------------------------------------------
extern "C" void kernel_launch(void* const* d_in, const int* in_sizes, int n_in,
                              void* d_out, int out_size) {
    const float* cp     = (const float*)d_in[0];   // center_pred (16,80,128,128)
    const float* wh     = (const float*)d_in[1];   // wh_pred     (16,2,128,128)
    const float* off    = (const float*)d_in[2];   // offset_pred (16,2,128,128)
    const float* boxes  = (const float*)d_in[3];   // (16,64,4)
    const int*   labels = (const int*)d_in[4];     // (16,64)
    float* out = (float*)d_out;

    k_fused<<<BG_BLOCKS + NB, 256>>>((const float4*)cp, boxes, labels,
                                     wh, off, out);
}